// round 5
// baseline (speedup 1.0000x reference)
#include <cuda_runtime.h>

#define Bn 256
#define Sn 196
#define Dn 2048
#define Hn 512
#define KSPLIT 32
#define KCHUNK (Dn / KSPLIT)   // 64
#define BK 16
#define TM 64
#define TN 128
#define ASTR 132   // 2*TM + 4 floats per k-row (A stored duplicated)
#define BSTR 132   // TN + 4

// Scratch (no cudaMalloc allowed)
__device__ __align__(16) float g_atth_part[KSPLIT * Bn * Hn];  // 16 MB partials
__device__ float g_atth[Bn * Hn];
__device__ float g_scores[Bn * Sn];

// Packed dual-FMA: d.lo += a.lo*b.lo; d.hi += a.hi*b.hi  (sm_100+)
__device__ __forceinline__ void ffma2(unsigned long long& d,
                                      unsigned long long a, unsigned long long b) {
    asm("fma.rn.f32x2 %0, %1, %2, %0;" : "+l"(d) : "l"(a), "l"(b));
}

// Hardware tanh approximation (MUFU.TANH, 1 instr, abs err ~5e-4)
__device__ __forceinline__ float htanh(float x) {
    float y;
    asm("tanh.approx.f32 %0, %1;" : "=f"(y) : "f"(x));
    return y;
}

// ---------------------------------------------------------------------------
// Kernel 1: split-K GEMM partials with packed f32x2 FMA.
//   part[z][m][n] = sum_{k in chunk z} h[m,k] * W[n,k]
// Tile 64m x 128n, BK=16, 256 threads, 8m x 4n per thread (16 f32x2 accs).
// A tile stored DUPLICATED ([k][2m] = {a,a}) so ld.shared.v2.u64 yields
// broadcast f32x2 operands with no pack movs; A-reads are warp-broadcast so
// the duplication is bandwidth-free. Grid (4, 4, 32) = 512 blocks.
// ---------------------------------------------------------------------------
__global__ __launch_bounds__(256) void k_h2att_sk(const float* __restrict__ A,
                                                  const float* __restrict__ W) {
    __shared__ __align__(16) float As[BK * ASTR];   // [k][2m] duplicated
    __shared__ __align__(16) float Bs[BK * BSTR];   // [k][n]
    const int tid = threadIdx.x;
    const int tx = tid & 31;          // n-quad (0..31) -> n = tx*4
    const int ty = tid >> 5;          // m-oct (0..7)   -> m = ty*8
    const int n0 = blockIdx.x * TN;
    const int m0 = blockIdx.y * TM;
    const int kbase = blockIdx.z * KCHUNK;

    unsigned long long acc[8][2];
#pragma unroll
    for (int i = 0; i < 8; i++) { acc[i][0] = 0ull; acc[i][1] = 0ull; }

    const int ar = tid >> 2;          // 0..63
    const int ac = (tid & 3) * 4;     // 0,4,8,12

    for (int kt = 0; kt < KCHUNK; kt += BK) {
        const int k0 = kbase + kt;
        // A fill (transposed + duplicated): 1 float4/thread
        {
            float4 a4 = *(const float4*)&A[(m0 + ar) * Dn + k0 + ac];
            *(float2*)&As[(ac + 0) * ASTR + 2 * ar] = make_float2(a4.x, a4.x);
            *(float2*)&As[(ac + 1) * ASTR + 2 * ar] = make_float2(a4.y, a4.y);
            *(float2*)&As[(ac + 2) * ASTR + 2 * ar] = make_float2(a4.z, a4.z);
            *(float2*)&As[(ac + 3) * ASTR + 2 * ar] = make_float2(a4.w, a4.w);
        }
        // B fill (transposed): 2 float4/thread
#pragma unroll
        for (int j = 0; j < 2; j++) {
            int idx = tid + j * 256;
            int br = idx >> 2;            // 0..127
            int bc = (idx & 3) * 4;
            float4 b4 = *(const float4*)&W[(n0 + br) * Dn + k0 + bc];
            Bs[(bc + 0) * BSTR + br] = b4.x;
            Bs[(bc + 1) * BSTR + br] = b4.y;
            Bs[(bc + 2) * BSTR + br] = b4.z;
            Bs[(bc + 3) * BSTR + br] = b4.w;
        }
        __syncthreads();
#pragma unroll
        for (int k = 0; k < BK; k++) {
            const ulonglong2* ap = (const ulonglong2*)&As[k * ASTR + ty * 16];
            ulonglong2 a01 = ap[0];   // {a_m,a_m},{a_m+1,a_m+1}
            ulonglong2 a23 = ap[1];
            ulonglong2 a45 = ap[2];
            ulonglong2 a67 = ap[3];
            ulonglong2 b = *(const ulonglong2*)&Bs[k * BSTR + tx * 4]; // {n0,n1},{n2,n3}
            ffma2(acc[0][0], a01.x, b.x); ffma2(acc[0][1], a01.x, b.y);
            ffma2(acc[1][0], a01.y, b.x); ffma2(acc[1][1], a01.y, b.y);
            ffma2(acc[2][0], a23.x, b.x); ffma2(acc[2][1], a23.x, b.y);
            ffma2(acc[3][0], a23.y, b.x); ffma2(acc[3][1], a23.y, b.y);
            ffma2(acc[4][0], a45.x, b.x); ffma2(acc[4][1], a45.x, b.y);
            ffma2(acc[5][0], a45.y, b.x); ffma2(acc[5][1], a45.y, b.y);
            ffma2(acc[6][0], a67.x, b.x); ffma2(acc[6][1], a67.x, b.y);
            ffma2(acc[7][0], a67.y, b.x); ffma2(acc[7][1], a67.y, b.y);
        }
        __syncthreads();
    }

    float* dst = g_atth_part + (size_t)blockIdx.z * (Bn * Hn);
#pragma unroll
    for (int i = 0; i < 8; i++) {
        ulonglong2 v; v.x = acc[i][0]; v.y = acc[i][1];   // 4 consecutive n
        *(ulonglong2*)&dst[(m0 + ty * 8 + i) * Hn + n0 + tx * 4] = v;
    }
}

// ---------------------------------------------------------------------------
// Kernel 2: reduce the 32 split-K partials + bias -> g_atth[B*H].
// 131072 elements, grid 512 x 256. L2-resident traffic.
// ---------------------------------------------------------------------------
__global__ __launch_bounds__(256) void k_reduce(const float* __restrict__ bias) {
    const int idx = blockIdx.x * 256 + threadIdx.x;   // b*Hn + h
    float acc = bias[idx & (Hn - 1)];
#pragma unroll
    for (int z = 0; z < KSPLIT; z++)
        acc += g_atth_part[z * (Bn * Hn) + idx];
    g_atth[idx] = acc;
}

// ---------------------------------------------------------------------------
// Kernel 3: raw scores, 2-slot ILP + hardware tanh. Grid (B, 7), 448 threads.
//   scores[b,s] = sum_h tanh(p[b,s,h] + att_h[b,h]) * w_alpha[h] + b_alpha
// ---------------------------------------------------------------------------
__global__ __launch_bounds__(448) void k_scores(const float* __restrict__ p_att,
                                                const float* __restrict__ w_alpha,
                                                const float* __restrict__ b_alpha) {
    __shared__ float ah[Hn];
    __shared__ float wa[Hn];

    const int b = blockIdx.x;
    const int sgrp = blockIdx.y;          // 0..6, 28 slots each
    const int tid = threadIdx.x;
    const int lane = tid & 31;
    const int warp = tid >> 5;            // 0..13

    for (int h = tid; h < Hn; h += 448) {
        ah[h] = g_atth[b * Hn + h];
        wa[h] = w_alpha[h];
    }
    __syncthreads();

    const float balpha = b_alpha[0];
    const float4* a4p = (const float4*)ah;
    const float4* w4p = (const float4*)wa;

    const int s0 = sgrp * 28 + warp * 2;
    const float4* pr0 = (const float4*)(p_att + ((long)b * Sn + s0) * Hn);
    const float4* pr1 = (const float4*)(p_att + ((long)b * Sn + s0 + 1) * Hn);

    float l0 = 0.0f, l1 = 0.0f;
#pragma unroll
    for (int i = 0; i < 4; i++) {
        const int h4 = i * 32 + lane;
        float4 pa = pr0[h4];
        float4 pb = pr1[h4];
        float4 a4 = a4p[h4];
        float4 w4 = w4p[h4];
        l0 += htanh(pa.x + a4.x) * w4.x;
        l1 += htanh(pb.x + a4.x) * w4.x;
        l0 += htanh(pa.y + a4.y) * w4.y;
        l1 += htanh(pb.y + a4.y) * w4.y;
        l0 += htanh(pa.z + a4.z) * w4.z;
        l1 += htanh(pb.z + a4.z) * w4.z;
        l0 += htanh(pa.w + a4.w) * w4.w;
        l1 += htanh(pb.w + a4.w) * w4.w;
    }
#pragma unroll
    for (int o = 16; o > 0; o >>= 1) {
        l0 += __shfl_xor_sync(0xffffffffu, l0, o);
        l1 += __shfl_xor_sync(0xffffffffu, l1, o);
    }
    if (lane == 0) {
        g_scores[b * Sn + s0]     = l0 + balpha;
        g_scores[b * Sn + s0 + 1] = l1 + balpha;
    }
}

// ---------------------------------------------------------------------------
// Kernel 4: fused masked-softmax prologue + weighted sum.
// Grid (4, B) x 128 threads. w_i = e_i*m_i / sum_j(e_j*m_j).
// ---------------------------------------------------------------------------
__global__ __launch_bounds__(128) void k_attres(const float* __restrict__ att_feats,
                                                const float* __restrict__ mask,
                                                float* __restrict__ out) {
    __shared__ float w[Sn];
    __shared__ float redm[4];
    __shared__ float reds[4];

    const int b = blockIdx.y;
    const int tid = threadIdx.x;
    const int lane = tid & 31;
    const int warp = tid >> 5;

    const float v0 = g_scores[b * Sn + tid];
    const float v1 = (tid + 128 < Sn) ? g_scores[b * Sn + tid + 128] : -3.402823e38f;

    float m = fmaxf(v0, v1);
#pragma unroll
    for (int o = 16; o > 0; o >>= 1)
        m = fmaxf(m, __shfl_xor_sync(0xffffffffu, m, o));
    if (lane == 0) redm[warp] = m;
    __syncthreads();
    m = fmaxf(fmaxf(redm[0], redm[1]), fmaxf(redm[2], redm[3]));

    float e0 = __expf(v0 - m) * mask[b * Sn + tid];
    float e1 = (tid + 128 < Sn) ? __expf(v1 - m) * mask[b * Sn + tid + 128] : 0.0f;
    float s = e0 + e1;
#pragma unroll
    for (int o = 16; o > 0; o >>= 1)
        s += __shfl_xor_sync(0xffffffffu, s, o);
    if (lane == 0) reds[warp] = s;
    __syncthreads();
    const float inv = 1.0f / (reds[0] + reds[1] + reds[2] + reds[3]);

    w[tid] = e0 * inv;
    if (tid + 128 < Sn) w[tid + 128] = e1 * inv;
    __syncthreads();

    const int d0 = blockIdx.x * 512 + tid * 4;
    const float* base = att_feats + (long)b * Sn * Dn + d0;

    float4 acc = make_float4(0.f, 0.f, 0.f, 0.f);
#pragma unroll 8
    for (int s2 = 0; s2 < Sn; s2++) {
        float4 f = *(const float4*)(base + (long)s2 * Dn);
        float ws = w[s2];
        acc.x += ws * f.x;
        acc.y += ws * f.y;
        acc.z += ws * f.z;
        acc.w += ws * f.w;
    }
    *(float4*)(out + (long)b * Dn + d0) = acc;
}

// ---------------------------------------------------------------------------

extern "C" void kernel_launch(void* const* d_in, const int* in_sizes, int n_in,
                              void* d_out, int out_size) {
    const float* h         = (const float*)d_in[0];  // [B, D]
    const float* att_feats = (const float*)d_in[1];  // [B, S, D]
    const float* p_att     = (const float*)d_in[2];  // [B, S, H]
    const float* mask      = (const float*)d_in[3];  // [B, S]
    const float* W_h2att   = (const float*)d_in[4];  // [H, D]
    const float* b_h2att   = (const float*)d_in[5];  // [H]
    const float* w_alpha   = (const float*)d_in[6];  // [H]
    const float* b_alpha   = (const float*)d_in[7];  // scalar
    float* out = (float*)d_out;                      // [B, D]

    (void)in_sizes; (void)n_in; (void)out_size;

    dim3 g1(TN == 128 ? Hn / TN : 4, Bn / TM, KSPLIT);  // (4, 4, 32) = 512 blocks
    k_h2att_sk<<<g1, 256>>>(h, W_h2att);

    k_reduce<<<(Bn * Hn) / 256, 256>>>(b_h2att);

    dim3 g3(Bn, 7);                     // 1792 blocks, 448 thr
    k_scores<<<g3, 448>>>(p_att, w_alpha, b_alpha);

    dim3 g4(4, Bn);                     // 1024 blocks
    k_attres<<<g4, 128>>>(att_feats, mask, out);
}

// round 6
// speedup vs baseline: 1.0212x; 1.0212x over previous
#include <cuda_runtime.h>

#define Bn 256
#define Sn 196
#define Dn 2048
#define Hn 512
#define KSPLIT 8
#define KCHUNK (Dn / KSPLIT)   // 256
#define BK 16
#define TM 64
#define TN 64
#define TSTR 68    // tile row stride (floats): 64 + 4, keeps 16B alignment

// Scratch (no cudaMalloc allowed)
__device__ __align__(16) float g_atth_part[KSPLIT * Bn * Hn];  // 4 MB partials
__device__ float g_scores[Bn * Sn];

// Hardware tanh approximation (MUFU.TANH, 1 instr, abs err ~5e-4; validated
// end-to-end rel_err 2.6e-6 in R5)
__device__ __forceinline__ float htanh(float x) {
    float y;
    asm("tanh.approx.f32 %0, %1;" : "=f"(y) : "f"(x));
    return y;
}

// ---------------------------------------------------------------------------
// Kernel 1: split-K GEMM partials.
//   part[z][m][n] = sum_{k in chunk z} h[m,k] * W[n,k]
// Tile 64m x 64n, BK=16, 256 threads, 4m x 4n per thread:
// 2 LDS.128 per 16 FFMA (vs 2 LDS per 8 FFMA in R4 -> half the issue load).
// Grid (8, 4, 8) = 256 blocks, ~14 warps/SM.
// ---------------------------------------------------------------------------
__global__ __launch_bounds__(256) void k_h2att_sk(const float* __restrict__ A,
                                                  const float* __restrict__ W) {
    __shared__ __align__(16) float As[BK * TSTR];   // [k][m]
    __shared__ __align__(16) float Bs[BK * TSTR];   // [k][n]
    const int tid = threadIdx.x;
    const int tx = tid & 15;          // n-quad -> n = tx*4
    const int ty = tid >> 4;          // m-quad -> m = ty*4
    const int n0 = blockIdx.x * TN;
    const int m0 = blockIdx.y * TM;
    const int kbase = blockIdx.z * KCHUNK;

    float acc[4][4] = {};

    const int fr = tid >> 2;          // 0..63 (tile row for fills)
    const int fc = (tid & 3) * 4;     // 0,4,8,12 (k offset for fills)

    for (int kt = 0; kt < KCHUNK; kt += BK) {
        const int k0 = kbase + kt;
        // Fills: one float4 along k per thread per tile (coalesced gmem).
        {
            float4 a4 = *(const float4*)&A[(m0 + fr) * Dn + k0 + fc];
            As[(fc + 0) * TSTR + fr] = a4.x;
            As[(fc + 1) * TSTR + fr] = a4.y;
            As[(fc + 2) * TSTR + fr] = a4.z;
            As[(fc + 3) * TSTR + fr] = a4.w;
            float4 b4 = *(const float4*)&W[(n0 + fr) * Dn + k0 + fc];
            Bs[(fc + 0) * TSTR + fr] = b4.x;
            Bs[(fc + 1) * TSTR + fr] = b4.y;
            Bs[(fc + 2) * TSTR + fr] = b4.z;
            Bs[(fc + 3) * TSTR + fr] = b4.w;
        }
        __syncthreads();
#pragma unroll
        for (int k = 0; k < BK; k++) {
            float4 a = *(const float4*)&As[k * TSTR + ty * 4];
            float4 b = *(const float4*)&Bs[k * TSTR + tx * 4];
            acc[0][0] += a.x * b.x; acc[0][1] += a.x * b.y;
            acc[0][2] += a.x * b.z; acc[0][3] += a.x * b.w;
            acc[1][0] += a.y * b.x; acc[1][1] += a.y * b.y;
            acc[1][2] += a.y * b.z; acc[1][3] += a.y * b.w;
            acc[2][0] += a.z * b.x; acc[2][1] += a.z * b.y;
            acc[2][2] += a.z * b.z; acc[2][3] += a.z * b.w;
            acc[3][0] += a.w * b.x; acc[3][1] += a.w * b.y;
            acc[3][2] += a.w * b.z; acc[3][3] += a.w * b.w;
        }
        __syncthreads();
    }

    float* dst = g_atth_part + (size_t)blockIdx.z * (Bn * Hn);
#pragma unroll
    for (int i = 0; i < 4; i++) {
        float4 v = make_float4(acc[i][0], acc[i][1], acc[i][2], acc[i][3]);
        *(float4*)&dst[(m0 + ty * 4 + i) * Hn + n0 + tx * 4] = v;
    }
}

// ---------------------------------------------------------------------------
// Kernel 2: raw scores, 2-slot ILP + hardware tanh. Grid (B, 7), 448 threads.
//   scores[b,s] = sum_h tanh(p[b,s,h] + att_h[b,h]) * w_alpha[h] + b_alpha
// att_h assembled from the 8 split-K partials + bias (L2-hit loads).
// ---------------------------------------------------------------------------
__global__ __launch_bounds__(448) void k_scores(const float* __restrict__ p_att,
                                                const float* __restrict__ w_alpha,
                                                const float* __restrict__ bias,
                                                const float* __restrict__ b_alpha) {
    __shared__ float ah[Hn];
    __shared__ float wa[Hn];

    const int b = blockIdx.x;
    const int sgrp = blockIdx.y;          // 0..6, 28 slots each
    const int tid = threadIdx.x;
    const int lane = tid & 31;
    const int warp = tid >> 5;            // 0..13

    for (int h = tid; h < Hn; h += 448) {
        float acc = bias[h];
#pragma unroll
        for (int z = 0; z < KSPLIT; z++)
            acc += g_atth_part[z * (Bn * Hn) + b * Hn + h];
        ah[h] = acc;
        wa[h] = w_alpha[h];
    }
    __syncthreads();

    const float balpha = b_alpha[0];
    const float4* a4p = (const float4*)ah;
    const float4* w4p = (const float4*)wa;

    const int s0 = sgrp * 28 + warp * 2;
    const float4* pr0 = (const float4*)(p_att + ((long)b * Sn + s0) * Hn);
    const float4* pr1 = (const float4*)(p_att + ((long)b * Sn + s0 + 1) * Hn);

    float l0 = 0.0f, l1 = 0.0f;
#pragma unroll
    for (int i = 0; i < 4; i++) {
        const int h4 = i * 32 + lane;
        float4 pa = pr0[h4];
        float4 pb = pr1[h4];
        float4 a4 = a4p[h4];
        float4 w4 = w4p[h4];
        l0 += htanh(pa.x + a4.x) * w4.x;
        l1 += htanh(pb.x + a4.x) * w4.x;
        l0 += htanh(pa.y + a4.y) * w4.y;
        l1 += htanh(pb.y + a4.y) * w4.y;
        l0 += htanh(pa.z + a4.z) * w4.z;
        l1 += htanh(pb.z + a4.z) * w4.z;
        l0 += htanh(pa.w + a4.w) * w4.w;
        l1 += htanh(pb.w + a4.w) * w4.w;
    }
#pragma unroll
    for (int o = 16; o > 0; o >>= 1) {
        l0 += __shfl_xor_sync(0xffffffffu, l0, o);
        l1 += __shfl_xor_sync(0xffffffffu, l1, o);
    }
    if (lane == 0) {
        g_scores[b * Sn + s0]     = l0 + balpha;
        g_scores[b * Sn + s0 + 1] = l1 + balpha;
    }
}

// ---------------------------------------------------------------------------
// Kernel 3: fused masked-softmax prologue + weighted sum.
// Grid (4, B) x 128 threads. w_i = e_i*m_i / sum_j(e_j*m_j).
// ---------------------------------------------------------------------------
__global__ __launch_bounds__(128) void k_attres(const float* __restrict__ att_feats,
                                                const float* __restrict__ mask,
                                                float* __restrict__ out) {
    __shared__ float w[Sn];
    __shared__ float redm[4];
    __shared__ float reds[4];

    const int b = blockIdx.y;
    const int tid = threadIdx.x;
    const int lane = tid & 31;
    const int warp = tid >> 5;

    const float v0 = g_scores[b * Sn + tid];
    const float v1 = (tid + 128 < Sn) ? g_scores[b * Sn + tid + 128] : -3.402823e38f;

    float m = fmaxf(v0, v1);
#pragma unroll
    for (int o = 16; o > 0; o >>= 1)
        m = fmaxf(m, __shfl_xor_sync(0xffffffffu, m, o));
    if (lane == 0) redm[warp] = m;
    __syncthreads();
    m = fmaxf(fmaxf(redm[0], redm[1]), fmaxf(redm[2], redm[3]));

    float e0 = __expf(v0 - m) * mask[b * Sn + tid];
    float e1 = (tid + 128 < Sn) ? __expf(v1 - m) * mask[b * Sn + tid + 128] : 0.0f;
    float s = e0 + e1;
#pragma unroll
    for (int o = 16; o > 0; o >>= 1)
        s += __shfl_xor_sync(0xffffffffu, s, o);
    if (lane == 0) reds[warp] = s;
    __syncthreads();
    const float inv = 1.0f / (reds[0] + reds[1] + reds[2] + reds[3]);

    w[tid] = e0 * inv;
    if (tid + 128 < Sn) w[tid + 128] = e1 * inv;
    __syncthreads();

    const int d0 = blockIdx.x * 512 + tid * 4;
    const float* base = att_feats + (long)b * Sn * Dn + d0;

    float4 acc = make_float4(0.f, 0.f, 0.f, 0.f);
#pragma unroll 8
    for (int s2 = 0; s2 < Sn; s2++) {
        float4 f = *(const float4*)(base + (long)s2 * Dn);
        float ws = w[s2];
        acc.x += ws * f.x;
        acc.y += ws * f.y;
        acc.z += ws * f.z;
        acc.w += ws * f.w;
    }
    *(float4*)(out + (long)b * Dn + d0) = acc;
}

// ---------------------------------------------------------------------------

extern "C" void kernel_launch(void* const* d_in, const int* in_sizes, int n_in,
                              void* d_out, int out_size) {
    const float* h         = (const float*)d_in[0];  // [B, D]
    const float* att_feats = (const float*)d_in[1];  // [B, S, D]
    const float* p_att     = (const float*)d_in[2];  // [B, S, H]
    const float* mask      = (const float*)d_in[3];  // [B, S]
    const float* W_h2att   = (const float*)d_in[4];  // [H, D]
    const float* b_h2att   = (const float*)d_in[5];  // [H]
    const float* w_alpha   = (const float*)d_in[6];  // [H]
    const float* b_alpha   = (const float*)d_in[7];  // scalar
    float* out = (float*)d_out;                      // [B, D]

    (void)in_sizes; (void)n_in; (void)out_size;

    dim3 g1(Hn / TN, Bn / TM, KSPLIT);  // (8, 4, 8) = 256 blocks
    k_h2att_sk<<<g1, 256>>>(h, W_h2att);

    dim3 g2(Bn, 7);                     // 1792 blocks, 448 thr
    k_scores<<<g2, 448>>>(p_att, w_alpha, b_h2att, b_alpha);

    dim3 g3(4, Bn);                     // 1024 blocks
    k_attres<<<g3, 128>>>(att_feats, mask, out);
}

// round 7
// speedup vs baseline: 1.2124x; 1.1872x over previous
#include <cuda_runtime.h>

#define Bn 256
#define Sn 196
#define Dn 2048
#define Hn 512
#define KSPLIT 16
#define KCHUNK (Dn / KSPLIT)   // 128
#define BK 16
#define TM 64
#define TN 64
#define TSTR 68    // tile row stride (floats): 64 + 4, keeps 16B alignment

// Scratch (no cudaMalloc allowed)
__device__ __align__(16) float g_atth_part[KSPLIT * Bn * Hn];  // 8 MB partials
__device__ float g_scores[Bn * Sn];

// Hardware tanh approximation (MUFU.TANH, 1 instr; validated rel_err 2.6e-6)
__device__ __forceinline__ float htanh(float x) {
    float y;
    asm("tanh.approx.f32 %0, %1;" : "=f"(y) : "f"(x));
    return y;
}

// ---------------------------------------------------------------------------
// Kernel 1: split-K GEMM partials, software-pipelined.
//   part[z][m][n] = sum_{k in chunk z} h[m,k] * W[n,k]
// Tile 64m x 64n, BK=16, 256 threads, 4m x 4n per thread.
// Pipeline: STS(cur) -> sync -> LDG(next, in flight) -> compute -> sync.
// The 577-cyc global load overlaps the ~570-cyc compute phase.
// Grid (8, 4, 16) = 512 blocks -> ~27 warps/SM, balanced waves.
// ---------------------------------------------------------------------------
__global__ __launch_bounds__(256) void k_h2att_sk(const float* __restrict__ A,
                                                  const float* __restrict__ W) {
    __shared__ __align__(16) float As[BK * TSTR];   // [k][m]
    __shared__ __align__(16) float Bs[BK * TSTR];   // [k][n]
    const int tid = threadIdx.x;
    const int tx = tid & 15;          // n-quad -> n = tx*4
    const int ty = tid >> 4;          // m-quad -> m = ty*4
    const int n0 = blockIdx.x * TN;
    const int m0 = blockIdx.y * TM;
    const int kbase = blockIdx.z * KCHUNK;

    const int fr = tid >> 2;          // 0..63 (tile row for fills)
    const int fc = (tid & 3) * 4;     // 0,4,8,12 (k offset for fills)

    const float* aptr = &A[(m0 + fr) * Dn + kbase + fc];
    const float* bptr = &W[(n0 + fr) * Dn + kbase + fc];

    float acc[4][4] = {};

    // prologue: first tile into registers
    float4 a4 = *(const float4*)aptr;
    float4 b4 = *(const float4*)bptr;

    for (int kt = 0; kt < KCHUNK; kt += BK) {
        // store current tile to smem
        As[(fc + 0) * TSTR + fr] = a4.x;
        As[(fc + 1) * TSTR + fr] = a4.y;
        As[(fc + 2) * TSTR + fr] = a4.z;
        As[(fc + 3) * TSTR + fr] = a4.w;
        Bs[(fc + 0) * TSTR + fr] = b4.x;
        Bs[(fc + 1) * TSTR + fr] = b4.y;
        Bs[(fc + 2) * TSTR + fr] = b4.z;
        Bs[(fc + 3) * TSTR + fr] = b4.w;
        __syncthreads();

        // prefetch next tile (LDG stays in flight through the compute phase)
        if (kt + BK < KCHUNK) {
            a4 = *(const float4*)(aptr + kt + BK);
            b4 = *(const float4*)(bptr + kt + BK);
        }

#pragma unroll
        for (int k = 0; k < BK; k++) {
            float4 a = *(const float4*)&As[k * TSTR + ty * 4];
            float4 b = *(const float4*)&Bs[k * TSTR + tx * 4];
            acc[0][0] += a.x * b.x; acc[0][1] += a.x * b.y;
            acc[0][2] += a.x * b.z; acc[0][3] += a.x * b.w;
            acc[1][0] += a.y * b.x; acc[1][1] += a.y * b.y;
            acc[1][2] += a.y * b.z; acc[1][3] += a.y * b.w;
            acc[2][0] += a.z * b.x; acc[2][1] += a.z * b.y;
            acc[2][2] += a.z * b.z; acc[2][3] += a.z * b.w;
            acc[3][0] += a.w * b.x; acc[3][1] += a.w * b.y;
            acc[3][2] += a.w * b.z; acc[3][3] += a.w * b.w;
        }
        __syncthreads();
    }

    float* dst = g_atth_part + (size_t)blockIdx.z * (Bn * Hn);
#pragma unroll
    for (int i = 0; i < 4; i++) {
        float4 v = make_float4(acc[i][0], acc[i][1], acc[i][2], acc[i][3]);
        *(float4*)&dst[(m0 + ty * 4 + i) * Hn + n0 + tx * 4] = v;
    }
}

// ---------------------------------------------------------------------------
// Kernel 2: raw scores, 2-slot ILP + hardware tanh. Grid (B, 7), 448 threads.
//   scores[b,s] = sum_h tanh(p[b,s,h] + att_h[b,h]) * w_alpha[h] + b_alpha
// att_h assembled from the 16 split-K partials + bias (L2-hit loads).
// ---------------------------------------------------------------------------
__global__ __launch_bounds__(448) void k_scores(const float* __restrict__ p_att,
                                                const float* __restrict__ w_alpha,
                                                const float* __restrict__ bias,
                                                const float* __restrict__ b_alpha) {
    __shared__ float ah[Hn];
    __shared__ float wa[Hn];

    const int b = blockIdx.x;
    const int sgrp = blockIdx.y;          // 0..6, 28 slots each
    const int tid = threadIdx.x;
    const int lane = tid & 31;
    const int warp = tid >> 5;            // 0..13

    for (int h = tid; h < Hn; h += 448) {
        float acc = bias[h];
#pragma unroll
        for (int z = 0; z < KSPLIT; z++)
            acc += g_atth_part[z * (Bn * Hn) + b * Hn + h];
        ah[h] = acc;
        wa[h] = w_alpha[h];
    }
    __syncthreads();

    const float balpha = b_alpha[0];
    const float4* a4p = (const float4*)ah;
    const float4* w4p = (const float4*)wa;

    const int s0 = sgrp * 28 + warp * 2;
    const float4* pr0 = (const float4*)(p_att + ((long)b * Sn + s0) * Hn);
    const float4* pr1 = (const float4*)(p_att + ((long)b * Sn + s0 + 1) * Hn);

    float l0 = 0.0f, l1 = 0.0f;
#pragma unroll
    for (int i = 0; i < 4; i++) {
        const int h4 = i * 32 + lane;
        float4 pa = pr0[h4];
        float4 pb = pr1[h4];
        float4 a4 = a4p[h4];
        float4 w4 = w4p[h4];
        l0 += htanh(pa.x + a4.x) * w4.x;
        l1 += htanh(pb.x + a4.x) * w4.x;
        l0 += htanh(pa.y + a4.y) * w4.y;
        l1 += htanh(pb.y + a4.y) * w4.y;
        l0 += htanh(pa.z + a4.z) * w4.z;
        l1 += htanh(pb.z + a4.z) * w4.z;
        l0 += htanh(pa.w + a4.w) * w4.w;
        l1 += htanh(pb.w + a4.w) * w4.w;
    }
#pragma unroll
    for (int o = 16; o > 0; o >>= 1) {
        l0 += __shfl_xor_sync(0xffffffffu, l0, o);
        l1 += __shfl_xor_sync(0xffffffffu, l1, o);
    }
    if (lane == 0) {
        g_scores[b * Sn + s0]     = l0 + balpha;
        g_scores[b * Sn + s0 + 1] = l1 + balpha;
    }
}

// ---------------------------------------------------------------------------
// Kernel 3: fused masked-softmax prologue + weighted sum.
// Grid (4, B) x 128 threads. w_i = e_i*m_i / sum_j(e_j*m_j).
// ---------------------------------------------------------------------------
__global__ __launch_bounds__(128) void k_attres(const float* __restrict__ att_feats,
                                                const float* __restrict__ mask,
                                                float* __restrict__ out) {
    __shared__ float w[Sn];
    __shared__ float redm[4];
    __shared__ float reds[4];

    const int b = blockIdx.y;
    const int tid = threadIdx.x;
    const int lane = tid & 31;
    const int warp = tid >> 5;

    const float v0 = g_scores[b * Sn + tid];
    const float v1 = (tid + 128 < Sn) ? g_scores[b * Sn + tid + 128] : -3.402823e38f;

    float m = fmaxf(v0, v1);
#pragma unroll
    for (int o = 16; o > 0; o >>= 1)
        m = fmaxf(m, __shfl_xor_sync(0xffffffffu, m, o));
    if (lane == 0) redm[warp] = m;
    __syncthreads();
    m = fmaxf(fmaxf(redm[0], redm[1]), fmaxf(redm[2], redm[3]));

    float e0 = __expf(v0 - m) * mask[b * Sn + tid];
    float e1 = (tid + 128 < Sn) ? __expf(v1 - m) * mask[b * Sn + tid + 128] : 0.0f;
    float s = e0 + e1;
#pragma unroll
    for (int o = 16; o > 0; o >>= 1)
        s += __shfl_xor_sync(0xffffffffu, s, o);
    if (lane == 0) reds[warp] = s;
    __syncthreads();
    const float inv = 1.0f / (reds[0] + reds[1] + reds[2] + reds[3]);

    w[tid] = e0 * inv;
    if (tid + 128 < Sn) w[tid + 128] = e1 * inv;
    __syncthreads();

    const int d0 = blockIdx.x * 512 + tid * 4;
    const float* base = att_feats + (long)b * Sn * Dn + d0;

    float4 acc = make_float4(0.f, 0.f, 0.f, 0.f);
#pragma unroll 8
    for (int s2 = 0; s2 < Sn; s2++) {
        float4 f = *(const float4*)(base + (long)s2 * Dn);
        float ws = w[s2];
        acc.x += ws * f.x;
        acc.y += ws * f.y;
        acc.z += ws * f.z;
        acc.w += ws * f.w;
    }
    *(float4*)(out + (long)b * Dn + d0) = acc;
}

// ---------------------------------------------------------------------------

extern "C" void kernel_launch(void* const* d_in, const int* in_sizes, int n_in,
                              void* d_out, int out_size) {
    const float* h         = (const float*)d_in[0];  // [B, D]
    const float* att_feats = (const float*)d_in[1];  // [B, S, D]
    const float* p_att     = (const float*)d_in[2];  // [B, S, H]
    const float* mask      = (const float*)d_in[3];  // [B, S]
    const float* W_h2att   = (const float*)d_in[4];  // [H, D]
    const float* b_h2att   = (const float*)d_in[5];  // [H]
    const float* w_alpha   = (const float*)d_in[6];  // [H]
    const float* b_alpha   = (const float*)d_in[7];  // scalar
    float* out = (float*)d_out;                      // [B, D]

    (void)in_sizes; (void)n_in; (void)out_size;

    dim3 g1(Hn / TN, Bn / TM, KSPLIT);  // (8, 4, 16) = 512 blocks
    k_h2att_sk<<<g1, 256>>>(h, W_h2att);

    dim3 g2(Bn, 7);                     // 1792 blocks, 448 thr
    k_scores<<<g2, 448>>>(p_att, w_alpha, b_h2att, b_alpha);

    dim3 g3(4, Bn);                     // 1024 blocks
    k_attres<<<g3, 128>>>(att_feats, mask, out);
}